// round 7
// baseline (speedup 1.0000x reference)
#include <cuda_runtime.h>
#include <cstdint>

// ASG loss = FCC (log-partition over all paths) - FAC (forced alignment).
// T=512, B=32, V=512, L=128 (fixed by dataset).
//
// FCC: unnormalized probability recursion v' = exp(lp) * (E v), E in regs.
// Cluster of 8 CTAs per 2 batches. Per-step exchange uses SELF-SIGNALING
// st.async.v4.b32 (16B) stores carrying mbarrier complete_tx credits: no
// fence, no separate arrive, no __syncthreads in the loop. Each of 16 warps
// computes complete dot products for its 4 rows x 2 batches (lanes split j
// 16-way), reduces via a shuffle merge-tree, gathers the 8 results into 2
// lanes (4 rows each), and pushes ONE 16B message per (batch, rank):
// 256 messages/CTA/step instead of 1024 scalar stores. The destination
// tx-barrier (expect_tx = 4096 B) flips when all 1024 floats land.
// FAC: separate CTAs, 1 warp/batch, register-resident.

namespace {
constexpr int T_ = 512, B_ = 32, V_ = 512, L_ = 128;
constexpr int CSZ = 8;      // cluster size
constexpr int ISL = 64;     // i-rows per CTA
constexpr int NTHR = 512;
constexpr int NFCC = 16;    // FCC clusters (2 batches each)
constexpr float NEG = -1000000000.0f;
constexpr unsigned FILL_BYTES = 2u * V_ * 4u;   // 4096 B per fill
}

__device__ float g_fcc[B_];
__device__ float g_fac[B_];
__device__ unsigned g_done[B_];   // parity counter, never reset

static __device__ __forceinline__ unsigned cta_rank() {
    unsigned r; asm("mov.u32 %0, %%cluster_ctarank;" : "=r"(r)); return r;
}
static __device__ __forceinline__ unsigned su32(const void* p) {
    unsigned a;
    asm("{ .reg .u64 t; cvta.to.shared.u64 t, %1; cvt.u32.u64 %0, t; }"
        : "=r"(a) : "l"(p));
    return a;
}
static __device__ __forceinline__ unsigned mapa_r(unsigned a, unsigned r) {
    unsigned o;
    asm("mapa.shared::cluster.u32 %0, %1, %2;" : "=r"(o) : "r"(a), "r"(r));
    return o;
}
static __device__ __forceinline__ void csync() {
    asm volatile("barrier.cluster.arrive.aligned;" ::: "memory");
    asm volatile("barrier.cluster.wait.aligned;" ::: "memory");
}
static __device__ __forceinline__ void mbar_init(unsigned a, unsigned cnt) {
    asm volatile("mbarrier.init.shared.b64 [%0], %1;" :: "r"(a), "r"(cnt) : "memory");
}
static __device__ __forceinline__ void mbar_expect(unsigned a, unsigned tx) {
    asm volatile("mbarrier.arrive.expect_tx.shared.b64 _, [%0], %1;"
                 :: "r"(a), "r"(tx) : "memory");
}
// Self-signaling 16-byte remote store: data lands in peer SMEM, credits 16
// bytes on the peer's mbarrier when complete.
static __device__ __forceinline__ void st_async128(unsigned a, unsigned x, unsigned y,
                                                   unsigned z, unsigned w, unsigned mb) {
    asm volatile("st.async.shared::cluster.mbarrier::complete_tx::bytes.v4.b32 "
                 "[%0], {%1,%2,%3,%4}, [%5];"
                 :: "r"(a), "r"(x), "r"(y), "r"(z), "r"(w), "r"(mb) : "memory");
}
static __device__ __forceinline__ void mbar_wait(unsigned a, unsigned parity) {
    unsigned done;
    asm volatile(
        "{\n\t.reg .pred p;\n\t"
        "mbarrier.try_wait.parity.acquire.cluster.shared::cta.b64 p, [%1], %2;\n\t"
        "selp.b32 %0, 1, 0, p;\n\t}"
        : "=r"(done) : "r"(a), "r"(parity) : "memory");
    if (!done) {
        asm volatile(
            "{\n\t.reg .pred P1;\n\t"
            "WL_%=:\n\t"
            "mbarrier.try_wait.parity.acquire.cluster.shared::cta.b64 P1, [%0], %1, 0x989680;\n\t"
            "@P1 bra.uni WD_%=;\n\t"
            "bra.uni WL_%=;\n\t"
            "WD_%=:\n\t}"
            :: "r"(a), "r"(parity) : "memory");
    }
}
static __device__ __forceinline__ unsigned long long fma2(
    unsigned long long a, unsigned long long b, unsigned long long c) {
    unsigned long long d;
    asm("fma.rn.f32x2 %0, %1, %2, %3;" : "=l"(d) : "l"(a), "l"(b), "l"(c));
    return d;
}
static __device__ __forceinline__ unsigned long long packf2(float lo, float hi) {
    unsigned long long d;
    asm("mov.b64 %0, {%1,%2};" : "=l"(d) : "f"(lo), "f"(hi));
    return d;
}
static __device__ __forceinline__ float pairsum(unsigned long long a) {
    float lo, hi;
    asm("mov.b64 {%0,%1}, %2;" : "=f"(lo), "=f"(hi) : "l"(a));
    return lo + hi;
}
// Merge-reduce step: combine two per-lane partial vectors; lanes with
// (lane & m) carry the 'b' index forward.
static __device__ __forceinline__ float mrg(float a, float b, int m, int lane) {
    float send = (lane & m) ? a : b;
    float keep = (lane & m) ? b : a;
    return keep + __shfl_xor_sync(~0u, send, m);
}

// Second arriver (parity odd) of {fcc, fac} writes the output.
static __device__ __forceinline__ void publish(int b, float val, bool is_fcc,
                                               float* __restrict__ out) {
    if (is_fcc) g_fcc[b] = val; else g_fac[b] = val;
    __threadfence();
    unsigned old = atomicAdd(&g_done[b], 1u);
    if (old & 1u) {
        __threadfence();
        out[b] = g_fcc[b] - g_fac[b];
    }
}

__global__ void __launch_bounds__(NTHR, 1) __cluster_dims__(CSZ, 1, 1)
asg_main(const float* __restrict__ lp, const float* __restrict__ tr,
         const int* __restrict__ tgt, const int* __restrict__ ilen,
         const int* __restrict__ tlen, float* __restrict__ out)
{
    __shared__ __align__(16) float s_u[2][2][V_];        // double-buffered v
    __shared__ __align__(8) unsigned long long s_mbar[2];

    const int tid  = threadIdx.x;
    const int lane = tid & 31;
    const int wid  = tid >> 5;
    const int cid  = (int)blockIdx.x >> 3;

    if (cid < NFCC) {
        // =============================== FCC ===============================
        const unsigned r = cta_rank();
        const int b0 = 2 * cid, b1 = 2 * cid + 1;
        const int len0 = ilen[b0], len1 = ilen[b1];

        // Pusher lanes: lane 0 -> batch 0 rows 4w..4w+3; lane 4 -> batch 1.
        const bool isp = (lane == 0) || (lane == 4);
        const int pbb  = lane >> 2;                      // 0 or 1 on pushers
        const int prow = (int)r * ISL + wid * 4;         // base global row

        const unsigned ubase  = su32(&s_u[0][0][0]);
        const unsigned mloc0  = su32(&s_mbar[0]);
        const unsigned mdelta = mloc0 - ubase;
        unsigned pb[CSZ];
        #pragma unroll
        for (int rk = 0; rk < CSZ; ++rk) pb[rk] = mapa_r(ubase, (unsigned)rk);

        if (tid == 0) {
            mbar_init(mloc0, 1);
            mbar_init(mloc0 + 8, 1);
            mbar_expect(mloc0 + 8, FILL_BYTES);   // fill@t=0 targets mbar[1]
        }

        // E registers: warp w owns rows r*64 + 4w + rr (rr<4); lane owns
        // j in {4*lane + 128k + m}: conflict-free interleaved map.
        unsigned long long e2[32];
        #pragma unroll
        for (int rr = 0; rr < 4; ++rr) {
            const int row = (int)r * ISL + wid * 4 + rr;
            #pragma unroll
            for (int k = 0; k < 4; ++k) {
                float4 v4 = *(const float4*)(tr + (size_t)row * V_ + 4 * lane + 128 * k);
                e2[rr * 8 + 2 * k]     = packf2(__expf(v4.x), __expf(v4.y));
                e2[rr * 8 + 2 * k + 1] = packf2(__expf(v4.z), __expf(v4.w));
            }
        }

        // v_0 = exp(lp[0,b,:]); every CTA initializes buffer 0 locally.
        s_u[0][0][tid] = __expf(lp[(size_t)b0 * V_ + tid]);
        s_u[0][1][tid] = __expf(lp[(size_t)b1 * V_ + tid]);
        __syncthreads();
        csync();   // peers' mbar init + expect + buffers visible

        for (int t = 0; t < T_; ++t) {
            const int buf = t & 1;

            // Prefetch exp(lp[t+1]) for this pusher's 4 rows, before the wait
            float4 el4 = make_float4(0.f, 0.f, 0.f, 0.f);
            if (isp && t + 1 < T_) {
                const float4 l4 = *(const float4*)&lp[((size_t)(t + 1) * B_ +
                                                       (pbb ? b1 : b0)) * V_ + prow];
                el4.x = __expf(l4.x); el4.y = __expf(l4.y);
                el4.z = __expf(l4.z); el4.w = __expf(l4.w);
            }

            if (t) mbar_wait(mloc0 + (unsigned)buf * 8, (unsigned)(((t - 1) >> 1) & 1));

            // Arm this mbar for its next fill (fill@t+1), after its consume
            if (tid == 0 && t + 3 <= T_)
                mbar_expect(mloc0 + (unsigned)buf * 8, FILL_BYTES);

            // Score capture (once per batch): lse(alpha_t) = log sum_j v_j
            if (r == 0 && (wid == 8 || wid == 9)) {
                const int bs = wid - 8;
                if (t == (bs ? len1 : len0) - 1) {
                    float s = 0.f;
                    #pragma unroll
                    for (int k = 0; k < 16; ++k) s += s_u[buf][bs][lane + 32 * k];
                    #pragma unroll
                    for (int mk = 16; mk; mk >>= 1) s += __shfl_xor_sync(~0u, s, mk);
                    if (lane == 0) publish(bs ? b1 : b0, logf(s), true, out);
                }
            }
            if (t == T_ - 1) break;

            // Phase A: complete dots for 4 rows x 2 batches, lanes split j
            unsigned long long acc[4][2];
            #pragma unroll
            for (int rr = 0; rr < 4; ++rr) { acc[rr][0] = 0ull; acc[rr][1] = 0ull; }
            #pragma unroll
            for (int k = 0; k < 4; ++k) {
                ulonglong2 q0 = *(const ulonglong2*)&s_u[buf][0][4 * lane + 128 * k];
                ulonglong2 q1 = *(const ulonglong2*)&s_u[buf][1][4 * lane + 128 * k];
                #pragma unroll
                for (int rr = 0; rr < 4; ++rr) {
                    acc[rr][0] = fma2(e2[rr * 8 + 2 * k],     q0.x, acc[rr][0]);
                    acc[rr][0] = fma2(e2[rr * 8 + 2 * k + 1], q0.y, acc[rr][0]);
                    acc[rr][1] = fma2(e2[rr * 8 + 2 * k],     q1.x, acc[rr][1]);
                    acc[rr][1] = fma2(e2[rr * 8 + 2 * k + 1], q1.y, acc[rr][1]);
                }
            }

            // Merge-tree: lane (idx<<2) ends with total for f[idx] (idx=rr*2+bb)
            float f[8];
            #pragma unroll
            for (int rr = 0; rr < 4; ++rr) {
                f[rr * 2]     = pairsum(acc[rr][0]);
                f[rr * 2 + 1] = pairsum(acc[rr][1]);
            }
            float g0 = mrg(f[0], f[4], 16, lane);
            float g1 = mrg(f[1], f[5], 16, lane);
            float g2 = mrg(f[2], f[6], 8 + 16, lane & 16 ? 16 : 16), gtmp;  // placeholder (unused)
            (void)g2; (void)gtmp;
            float h0, h1, s;
            {
                float q2 = mrg(f[2], f[6], 16, lane);
                float q3 = mrg(f[3], f[7], 16, lane);
                h0 = mrg(g0, q2, 8, lane);
                h1 = mrg(g1, q3, 8, lane);
                s  = mrg(h0, h1, 4, lane);
                s += __shfl_xor_sync(~0u, s, 2);
                s += __shfl_xor_sync(~0u, s, 1);
            }

            // Gather the warp's 8 results into the 2 pusher lanes:
            // lane 0 <- lanes {0,8,16,24} (batch 0, rows 0..3)
            // lane 4 <- lanes {4,12,20,28} (batch 1, rows 0..3)
            const int gbase = lane & 7;
            float r0 = __shfl_sync(~0u, s, gbase);
            float r1 = __shfl_sync(~0u, s, gbase + 8);
            float r2 = __shfl_sync(~0u, s, gbase + 16);
            float r3 = __shfl_sync(~0u, s, gbase + 24);

            // One 16B self-signaling push per rank per pusher lane.
            if (isp) {
                const unsigned vx = __float_as_uint(el4.x * r0);
                const unsigned vy = __float_as_uint(el4.y * r1);
                const unsigned vz = __float_as_uint(el4.z * r2);
                const unsigned vw = __float_as_uint(el4.w * r3);
                const int nbuf = buf ^ 1;
                const unsigned off = ((unsigned)(nbuf * 2 + pbb) * V_ + (unsigned)prow) * 4u;
                const unsigned mboff = mdelta + (unsigned)nbuf * 8u;
                #pragma unroll
                for (int rk = 0; rk < CSZ; ++rk)
                    st_async128(pb[rk] + off, vx, vy, vz, vw, pb[rk] + mboff);
            }
        }
        csync();   // no CTA exits while peers may still write its SMEM
    } else {
        // =============================== FAC ===============================
        if (wid >= 4) return;
        const int b = ((int)blockIdx.x - NFCC * CSZ) * 4 + wid;   // 0..31
        const int il = ilen[b], tl = tlen[b];

        int tg[4];
        #pragma unroll
        for (int k = 0; k < 4; ++k) tg[k] = tgt[b * L_ + lane * 4 + k];

        float ts[4], tp[4];
        #pragma unroll
        for (int k = 0; k < 4; ++k) ts[k] = tr[tg[k] * V_ + tg[k]];
        const int tprev = __shfl_up_sync(~0u, tg[3], 1);
        tp[0] = tr[tg[0] * V_ + tprev];           // garbage on lane 0, never used
        tp[1] = tr[tg[1] * V_ + tg[0]];
        tp[2] = tr[tg[2] * V_ + tg[1]];
        tp[3] = tr[tg[3] * V_ + tg[2]];

        float beta[4];
        #pragma unroll
        for (int k = 0; k < 4; ++k)
            beta[k] = (lane == 0 && k == 0) ? lp[(size_t)b * V_ + tg[0]] : NEG;

        float emn[4];
        #pragma unroll
        for (int k = 0; k < 4; ++k)
            emn[k] = lp[((size_t)1 * B_ + b) * V_ + tg[k]];

        for (int t = 0; t < T_; ++t) {
            if (t == il - 1) {
                const int lsel = tl - 1;
                if (lane == (lsel >> 2)) publish(b, beta[lsel & 3], false, out);
            }
            if (t == T_ - 1) break;

            float em[4];
            #pragma unroll
            for (int k = 0; k < 4; ++k) em[k] = emn[k];
            if (t + 2 < T_) {
                #pragma unroll
                for (int k = 0; k < 4; ++k)
                    emn[k] = lp[((size_t)(t + 2) * B_ + b) * V_ + tg[k]];
            }

            const float bprev = __shfl_up_sync(~0u, beta[3], 1);
            float prevs[4] = {bprev, beta[0], beta[1], beta[2]};
            #pragma unroll
            for (int k = 0; k < 4; ++k) {
                float stay = beta[k] + ts[k];
                float move = (lane == 0 && k == 0) ? NEG : prevs[k] + tp[k];
                float hi = fmaxf(stay, move);
                float lo = fminf(stay, move);
                beta[k] = em[k] + hi + __logf(1.f + __expf(lo - hi));
            }
        }
    }
}

extern "C" void kernel_launch(void* const* d_in, const int* in_sizes, int n_in,
                              void* d_out, int out_size) {
    const float* lp  = (const float*)d_in[0];
    const float* tr  = (const float*)d_in[1];
    const int*   tgt = (const int*)d_in[2];
    const int*   il  = (const int*)d_in[3];
    const int*   tl  = (const int*)d_in[4];
    (void)in_sizes; (void)n_in; (void)out_size;

    asg_main<<<NFCC * CSZ + CSZ, NTHR>>>(lp, tr, tgt, il, tl, (float*)d_out);
}

// round 8
// speedup vs baseline: 1.1405x; 1.1405x over previous
#include <cuda_runtime.h>
#include <cstdint>

// ASG loss = FCC (log-partition over all paths) - FAC (forced alignment).
// T=512, B=32, V=512, L=128 (fixed by dataset).
//
// FCC: unnormalized probability recursion v' = exp(lp) * (E v), E in regs.
// Cluster of 8 CTAs per 2 batches. Per-step exchange uses SELF-SIGNALING
// st.async stores carrying mbarrier complete_tx credits: no fence, no
// separate arrive, no __syncthreads in the loop. Each of 16 warps computes
// complete dot products for its 4 rows x 2 batches (lanes split j 16-way),
// reduces via a shuffle merge-tree. Row results are PAIR-PACKED (one extra
// shfl) and pushed as 8-byte st.async.b64 messages: 512 messages/CTA/step
// (vs 1024 scalar in the previous best). Destination tx-barrier
// (expect_tx = 4096 B) flips when all 1024 floats land.
// FAC: separate CTAs, 1 warp/batch, register-resident.

namespace {
constexpr int T_ = 512, B_ = 32, V_ = 512, L_ = 128;
constexpr int CSZ = 8;      // cluster size
constexpr int ISL = 64;     // i-rows per CTA
constexpr int NTHR = 512;
constexpr int NFCC = 16;    // FCC clusters (2 batches each)
constexpr float NEG = -1000000000.0f;
constexpr unsigned FILL_BYTES = 2u * V_ * 4u;   // 4096 B per fill
}

__device__ float g_fcc[B_];
__device__ float g_fac[B_];
__device__ unsigned g_done[B_];   // parity counter, never reset

static __device__ __forceinline__ unsigned cta_rank() {
    unsigned r; asm("mov.u32 %0, %%cluster_ctarank;" : "=r"(r)); return r;
}
static __device__ __forceinline__ unsigned su32(const void* p) {
    unsigned a;
    asm("{ .reg .u64 t; cvta.to.shared.u64 t, %1; cvt.u32.u64 %0, t; }"
        : "=r"(a) : "l"(p));
    return a;
}
static __device__ __forceinline__ unsigned mapa_r(unsigned a, unsigned r) {
    unsigned o;
    asm("mapa.shared::cluster.u32 %0, %1, %2;" : "=r"(o) : "r"(a), "r"(r));
    return o;
}
static __device__ __forceinline__ void csync() {
    asm volatile("barrier.cluster.arrive.aligned;" ::: "memory");
    asm volatile("barrier.cluster.wait.aligned;" ::: "memory");
}
static __device__ __forceinline__ void mbar_init(unsigned a, unsigned cnt) {
    asm volatile("mbarrier.init.shared.b64 [%0], %1;" :: "r"(a), "r"(cnt) : "memory");
}
static __device__ __forceinline__ void mbar_expect(unsigned a, unsigned tx) {
    asm volatile("mbarrier.arrive.expect_tx.shared.b64 _, [%0], %1;"
                 :: "r"(a), "r"(tx) : "memory");
}
// Self-signaling 8-byte remote store: data lands in peer SMEM, credits 8
// bytes on the peer's mbarrier when complete.
static __device__ __forceinline__ void st_async64(unsigned a, unsigned long long v,
                                                  unsigned mb) {
    asm volatile("st.async.shared::cluster.mbarrier::complete_tx::bytes.b64 [%0], %1, [%2];"
                 :: "r"(a), "l"(v), "r"(mb) : "memory");
}
static __device__ __forceinline__ void mbar_wait(unsigned a, unsigned parity) {
    unsigned done;
    asm volatile(
        "{\n\t.reg .pred p;\n\t"
        "mbarrier.try_wait.parity.acquire.cluster.shared::cta.b64 p, [%1], %2;\n\t"
        "selp.b32 %0, 1, 0, p;\n\t}"
        : "=r"(done) : "r"(a), "r"(parity) : "memory");
    if (!done) {
        asm volatile(
            "{\n\t.reg .pred P1;\n\t"
            "WL_%=:\n\t"
            "mbarrier.try_wait.parity.acquire.cluster.shared::cta.b64 P1, [%0], %1, 0x989680;\n\t"
            "@P1 bra.uni WD_%=;\n\t"
            "bra.uni WL_%=;\n\t"
            "WD_%=:\n\t}"
            :: "r"(a), "r"(parity) : "memory");
    }
}
static __device__ __forceinline__ unsigned long long fma2(
    unsigned long long a, unsigned long long b, unsigned long long c) {
    unsigned long long d;
    asm("fma.rn.f32x2 %0, %1, %2, %3;" : "=l"(d) : "l"(a), "l"(b), "l"(c));
    return d;
}
static __device__ __forceinline__ unsigned long long packf2(float lo, float hi) {
    unsigned long long d;
    asm("mov.b64 %0, {%1,%2};" : "=l"(d) : "f"(lo), "f"(hi));
    return d;
}
static __device__ __forceinline__ float pairsum(unsigned long long a) {
    float lo, hi;
    asm("mov.b64 {%0,%1}, %2;" : "=f"(lo), "=f"(hi) : "l"(a));
    return lo + hi;
}
// Merge-reduce step: combine two per-lane partial vectors; lanes with
// (lane & m) carry the 'b' index forward.
static __device__ __forceinline__ float mrg(float a, float b, int m, int lane) {
    float send = (lane & m) ? a : b;
    float keep = (lane & m) ? b : a;
    return keep + __shfl_xor_sync(~0u, send, m);
}

// Second arriver (parity odd) of {fcc, fac} writes the output.
static __device__ __forceinline__ void publish(int b, float val, bool is_fcc,
                                               float* __restrict__ out) {
    if (is_fcc) g_fcc[b] = val; else g_fac[b] = val;
    __threadfence();
    unsigned old = atomicAdd(&g_done[b], 1u);
    if (old & 1u) {
        __threadfence();
        out[b] = g_fcc[b] - g_fac[b];
    }
}

__global__ void __launch_bounds__(NTHR, 1) __cluster_dims__(CSZ, 1, 1)
asg_main(const float* __restrict__ lp, const float* __restrict__ tr,
         const int* __restrict__ tgt, const int* __restrict__ ilen,
         const int* __restrict__ tlen, float* __restrict__ out)
{
    __shared__ __align__(16) float s_u[2][2][V_];        // double-buffered v
    __shared__ __align__(8) unsigned long long s_mbar[2];

    const int tid  = threadIdx.x;
    const int lane = tid & 31;
    const int wid  = tid >> 5;
    const int cid  = (int)blockIdx.x >> 3;

    if (cid < NFCC) {
        // =============================== FCC ===============================
        const unsigned r = cta_rank();
        const int b0 = 2 * cid, b1 = 2 * cid + 1;
        const int len0 = ilen[b0], len1 = ilen[b1];

        // Value lanes: lanes 0,4,...,28 hold the 8 final sums (idx = lane>>2,
        // idx = rr*2 + bb). Pair-pusher lanes: idx in {0,1,4,5} push rows
        // (rr, rr+1) of batch bb as one 8B message.
        const bool isv = (lane & 3) == 0;
        const int idx = lane >> 2;               // 0..7 meaningful on isv lanes
        const int prr = idx >> 1, pbb = idx & 1;
        const int prow = (int)r * ISL + wid * 4 + prr;   // global row (el / push base)
        const bool isp = isv && ((idx & 1) == (idx >> 1 & 1) * 0 ? (idx == 0 || idx == 1 || idx == 4 || idx == 5) : false);
        // (simplified below; kept literal for clarity)
        const bool isp2 = (lane == 0) || (lane == 4) || (lane == 16) || (lane == 20);

        const unsigned ubase  = su32(&s_u[0][0][0]);
        const unsigned mloc0  = su32(&s_mbar[0]);
        const unsigned mdelta = mloc0 - ubase;
        unsigned pb[CSZ];
        #pragma unroll
        for (int rk = 0; rk < CSZ; ++rk) pb[rk] = mapa_r(ubase, (unsigned)rk);

        if (tid == 0) {
            mbar_init(mloc0, 1);
            mbar_init(mloc0 + 8, 1);
            mbar_expect(mloc0 + 8, FILL_BYTES);   // fill@t=0 targets mbar[1]
        }

        // E registers: warp w owns rows r*64 + 4w + rr (rr<4); lane owns
        // j in {4*lane + 128k + m}: conflict-free interleaved map.
        unsigned long long e2[32];
        #pragma unroll
        for (int rr = 0; rr < 4; ++rr) {
            const int row = (int)r * ISL + wid * 4 + rr;
            #pragma unroll
            for (int k = 0; k < 4; ++k) {
                float4 v4 = *(const float4*)(tr + (size_t)row * V_ + 4 * lane + 128 * k);
                e2[rr * 8 + 2 * k]     = packf2(__expf(v4.x), __expf(v4.y));
                e2[rr * 8 + 2 * k + 1] = packf2(__expf(v4.z), __expf(v4.w));
            }
        }

        // v_0 = exp(lp[0,b,:]); every CTA initializes buffer 0 locally.
        s_u[0][0][tid] = __expf(lp[(size_t)b0 * V_ + tid]);
        s_u[0][1][tid] = __expf(lp[(size_t)b1 * V_ + tid]);
        __syncthreads();
        csync();   // peers' mbar init + expect + buffers visible

        for (int t = 0; t < T_; ++t) {
            const int buf = t & 1;

            // Prefetch exp(lp[t+1]) for this lane's (row,batch), before wait
            float el = 0.f;
            if (isv && t + 1 < T_)
                el = __expf(lp[((size_t)(t + 1) * B_ + (pbb ? b1 : b0)) * V_ + prow]);

            if (t) mbar_wait(mloc0 + (unsigned)buf * 8, (unsigned)(((t - 1) >> 1) & 1));

            // Arm this mbar for its next fill (fill@t+1), after its consume
            if (tid == 0 && t + 3 <= T_)
                mbar_expect(mloc0 + (unsigned)buf * 8, FILL_BYTES);

            // Score capture (once per batch): lse(alpha_t) = log sum_j v_j
            if (r == 0 && (wid == 8 || wid == 9)) {
                const int bs = wid - 8;
                if (t == (bs ? len1 : len0) - 1) {
                    float s = 0.f;
                    #pragma unroll
                    for (int k = 0; k < 16; ++k) s += s_u[buf][bs][lane + 32 * k];
                    #pragma unroll
                    for (int mk = 16; mk; mk >>= 1) s += __shfl_xor_sync(~0u, s, mk);
                    if (lane == 0) publish(bs ? b1 : b0, logf(s), true, out);
                }
            }
            if (t == T_ - 1) break;

            // Phase A: complete dots for 4 rows x 2 batches, lanes split j
            unsigned long long acc[4][2];
            #pragma unroll
            for (int rr = 0; rr < 4; ++rr) { acc[rr][0] = 0ull; acc[rr][1] = 0ull; }
            #pragma unroll
            for (int k = 0; k < 4; ++k) {
                ulonglong2 q0 = *(const ulonglong2*)&s_u[buf][0][4 * lane + 128 * k];
                ulonglong2 q1 = *(const ulonglong2*)&s_u[buf][1][4 * lane + 128 * k];
                #pragma unroll
                for (int rr = 0; rr < 4; ++rr) {
                    acc[rr][0] = fma2(e2[rr * 8 + 2 * k],     q0.x, acc[rr][0]);
                    acc[rr][0] = fma2(e2[rr * 8 + 2 * k + 1], q0.y, acc[rr][0]);
                    acc[rr][1] = fma2(e2[rr * 8 + 2 * k],     q1.x, acc[rr][1]);
                    acc[rr][1] = fma2(e2[rr * 8 + 2 * k + 1], q1.y, acc[rr][1]);
                }
            }

            // Merge-tree: lane (idx<<2) ends with total for f[idx] (idx=rr*2+bb)
            float f[8];
            #pragma unroll
            for (int rr = 0; rr < 4; ++rr) {
                f[rr * 2]     = pairsum(acc[rr][0]);
                f[rr * 2 + 1] = pairsum(acc[rr][1]);
            }
            float g0 = mrg(f[0], f[4], 16, lane);
            float g1 = mrg(f[1], f[5], 16, lane);
            float g2 = mrg(f[2], f[6], 16, lane);
            float g3 = mrg(f[3], f[7], 16, lane);
            float h0 = mrg(g0, g2, 8, lane);
            float h1 = mrg(g1, g3, 8, lane);
            float s  = mrg(h0, h1, 4, lane);
            s += __shfl_xor_sync(~0u, s, 2);
            s += __shfl_xor_sync(~0u, s, 1);

            // v' on the 8 value lanes; pair rows (rr, rr+1) with ONE shfl,
            // then lanes {0,4,16,20} push one 8B self-signaling message per rank.
            const float v = el * s;
            const float vh = __shfl_down_sync(~0u, v, 8);   // idx+2: row rr+1, same bb
            if (isp2) {
                const unsigned long long pv = packf2(v, vh);
                const int nbuf = buf ^ 1;
                const unsigned off = ((unsigned)(nbuf * 2 + pbb) * V_ + (unsigned)prow) * 4u;
                const unsigned mboff = mdelta + (unsigned)nbuf * 8u;
                #pragma unroll
                for (int rk = 0; rk < CSZ; ++rk)
                    st_async64(pb[rk] + off, pv, pb[rk] + mboff);
            }
            (void)isp;
        }
        csync();   // no CTA exits while peers may still write its SMEM
    } else {
        // =============================== FAC ===============================
        if (wid >= 4) return;
        const int b = ((int)blockIdx.x - NFCC * CSZ) * 4 + wid;   // 0..31
        const int il = ilen[b], tl = tlen[b];

        int tg[4];
        #pragma unroll
        for (int k = 0; k < 4; ++k) tg[k] = tgt[b * L_ + lane * 4 + k];

        float ts[4], tp[4];
        #pragma unroll
        for (int k = 0; k < 4; ++k) ts[k] = tr[tg[k] * V_ + tg[k]];
        const int tprev = __shfl_up_sync(~0u, tg[3], 1);
        tp[0] = tr[tg[0] * V_ + tprev];           // garbage on lane 0, never used
        tp[1] = tr[tg[1] * V_ + tg[0]];
        tp[2] = tr[tg[2] * V_ + tg[1]];
        tp[3] = tr[tg[3] * V_ + tg[2]];

        float beta[4];
        #pragma unroll
        for (int k = 0; k < 4; ++k)
            beta[k] = (lane == 0 && k == 0) ? lp[(size_t)b * V_ + tg[0]] : NEG;

        float emn[4];
        #pragma unroll
        for (int k = 0; k < 4; ++k)
            emn[k] = lp[((size_t)1 * B_ + b) * V_ + tg[k]];

        for (int t = 0; t < T_; ++t) {
            if (t == il - 1) {
                const int lsel = tl - 1;
                if (lane == (lsel >> 2)) publish(b, beta[lsel & 3], false, out);
            }
            if (t == T_ - 1) break;

            float em[4];
            #pragma unroll
            for (int k = 0; k < 4; ++k) em[k] = emn[k];
            if (t + 2 < T_) {
                #pragma unroll
                for (int k = 0; k < 4; ++k)
                    emn[k] = lp[((size_t)(t + 2) * B_ + b) * V_ + tg[k]];
            }

            const float bprev = __shfl_up_sync(~0u, beta[3], 1);
            float prevs[4] = {bprev, beta[0], beta[1], beta[2]};
            #pragma unroll
            for (int k = 0; k < 4; ++k) {
                float stay = beta[k] + ts[k];
                float move = (lane == 0 && k == 0) ? NEG : prevs[k] + tp[k];
                float hi = fmaxf(stay, move);
                float lo = fminf(stay, move);
                beta[k] = em[k] + hi + __logf(1.f + __expf(lo - hi));
            }
        }
    }
}

extern "C" void kernel_launch(void* const* d_in, const int* in_sizes, int n_in,
                              void* d_out, int out_size) {
    const float* lp  = (const float*)d_in[0];
    const float* tr  = (const float*)d_in[1];
    const int*   tgt = (const int*)d_in[2];
    const int*   il  = (const int*)d_in[3];
    const int*   tl  = (const int*)d_in[4];
    (void)in_sizes; (void)n_in; (void)out_size;

    asg_main<<<NFCC * CSZ + CSZ, NTHR>>>(lp, tr, tgt, il, tl, (float*)d_out);
}